// round 1
// baseline (speedup 1.0000x reference)
#include <cuda_runtime.h>
#include <math.h>

#define B_ 8
#define T_ 2048
#define C_ 1024
#define H_ 64
#define NROWS (B_ * T_)   // 16384

// Scratch (only used when the harness output doesn't include a given tensor)
__device__ float g_q[NROWS * H_];
__device__ float g_k[NROWS * H_];
__device__ float g_v[NROWS * H_];
__device__ float g_res[NROWS * H_];
__device__ float g_attn_scratch[(size_t)B_ * T_ * T_];

// ---------------------------------------------------------------------------
// Kernel 1: QKV projection. grid = (NROWS/64, 1, 3), block = 256.
// Computes out[row, h] = sum_c x[row, c] * W[c, h] for W in {Wq, Wk, Wv}.
// ---------------------------------------------------------------------------
__global__ void proj_kernel(const float* __restrict__ x,
                            const float* __restrict__ Wq,
                            const float* __restrict__ Wk,
                            const float* __restrict__ Wv) {
    __shared__ float sx[64][65];
    __shared__ float sw[64][65];

    const float* W;
    float* out;
    if (blockIdx.z == 0)      { W = Wq; out = g_q; }
    else if (blockIdx.z == 1) { W = Wk; out = g_k; }
    else                      { W = Wv; out = g_v; }

    const int row0 = blockIdx.x * 64;
    const int tx = threadIdx.x & 15;   // 16 cols of threads
    const int ty = threadIdx.x >> 4;   // 16 rows of threads

    float acc[4][4] = {};

    for (int k0 = 0; k0 < C_; k0 += 64) {
        for (int i = threadIdx.x; i < 64 * 64; i += 256) {
            int r = i >> 6, c = i & 63;
            sx[r][c] = x[(size_t)(row0 + r) * C_ + (k0 + c)];
            sw[r][c] = W[(size_t)(k0 + r) * H_ + c];
        }
        __syncthreads();

        #pragma unroll
        for (int kk = 0; kk < 64; kk++) {
            float a[4], b[4];
            #pragma unroll
            for (int i = 0; i < 4; i++) a[i] = sx[ty * 4 + i][kk];
            #pragma unroll
            for (int j = 0; j < 4; j++) b[j] = sw[kk][tx * 4 + j];
            #pragma unroll
            for (int i = 0; i < 4; i++)
                #pragma unroll
                for (int j = 0; j < 4; j++)
                    acc[i][j] = fmaf(a[i], b[j], acc[i][j]);
        }
        __syncthreads();
    }

    #pragma unroll
    for (int i = 0; i < 4; i++)
        #pragma unroll
        for (int j = 0; j < 4; j++)
            out[(size_t)(row0 + ty * 4 + i) * H_ + tx * 4 + j] = acc[i][j];
}

// ---------------------------------------------------------------------------
// Kernel 2: raw scores S = Q @ K^T / 32 for lower-triangular 64x64 tiles.
// grid = (32 s-tiles, 32 t-tiles, 8 batches), block = 256.
// Upper-triangular tiles are skipped entirely (softmax masks by index).
// ---------------------------------------------------------------------------
__global__ void scores_kernel(float* __restrict__ attn) {
    const int s_t = blockIdx.x;
    const int t_t = blockIdx.y;
    if (s_t > t_t) return;
    const int b = blockIdx.z;

    __shared__ float sq[64][65];
    __shared__ float sk[64][65];

    const float* q = g_q + (size_t)b * T_ * H_;
    const float* k = g_k + (size_t)b * T_ * H_;
    const int t0 = t_t * 64;
    const int s0 = s_t * 64;

    for (int i = threadIdx.x; i < 64 * 64; i += 256) {
        int r = i >> 6, c = i & 63;
        sq[r][c] = q[(size_t)(t0 + r) * H_ + c];
        sk[r][c] = k[(size_t)(s0 + r) * H_ + c];
    }
    __syncthreads();

    const int tx = threadIdx.x & 15;
    const int ty = threadIdx.x >> 4;

    float acc[4][4] = {};
    #pragma unroll
    for (int kk = 0; kk < 64; kk++) {
        float a[4], bb[4];
        #pragma unroll
        for (int i = 0; i < 4; i++) a[i] = sq[ty * 4 + i][kk];
        #pragma unroll
        for (int j = 0; j < 4; j++) bb[j] = sk[tx * 4 + j][kk];
        #pragma unroll
        for (int i = 0; i < 4; i++)
            #pragma unroll
            for (int j = 0; j < 4; j++)
                acc[i][j] = fmaf(a[i], bb[j], acc[i][j]);
    }

    const float inv_scale = 0.03125f;  // 1/sqrt(1024)
    #pragma unroll
    for (int i = 0; i < 4; i++) {
        size_t row = (size_t)b * T_ + t0 + ty * 4 + i;
        #pragma unroll
        for (int j = 0; j < 4; j++)
            attn[row * T_ + s0 + tx * 4 + j] = acc[i][j] * inv_scale;
    }
}

// ---------------------------------------------------------------------------
// Kernel 3: row-wise causal softmax over attn, in place.
// grid = 16384 (one row each), block = 256, 8 elements/thread.
// Masked (s > t) entries are written as exact 0.
// ---------------------------------------------------------------------------
__global__ void softmax_kernel(float* __restrict__ attn) {
    const int row = blockIdx.x;           // b * T_ + t
    const int t = row & (T_ - 1);
    float* p = attn + (size_t)row * T_;

    __shared__ float red_max[8];
    __shared__ float red_sum[8];

    float vals[8];
    float mx = -INFINITY;
    #pragma unroll
    for (int j = 0; j < 8; j++) {
        int s = threadIdx.x + j * 256;
        vals[j] = (s <= t) ? p[s] : -INFINITY;
        mx = fmaxf(mx, vals[j]);
    }
    #pragma unroll
    for (int o = 16; o; o >>= 1) mx = fmaxf(mx, __shfl_xor_sync(0xffffffffu, mx, o));
    if ((threadIdx.x & 31) == 0) red_max[threadIdx.x >> 5] = mx;
    __syncthreads();
    float m = red_max[0];
    #pragma unroll
    for (int w = 1; w < 8; w++) m = fmaxf(m, red_max[w]);

    float sum = 0.f;
    #pragma unroll
    for (int j = 0; j < 8; j++) {
        vals[j] = __expf(vals[j] - m);    // exp(-inf) == 0 for masked
        sum += vals[j];
    }
    #pragma unroll
    for (int o = 16; o; o >>= 1) sum += __shfl_xor_sync(0xffffffffu, sum, o);
    if ((threadIdx.x & 31) == 0) red_sum[threadIdx.x >> 5] = sum;
    __syncthreads();
    float total = 0.f;
    #pragma unroll
    for (int w = 0; w < 8; w++) total += red_sum[w];

    const float inv = 1.f / total;
    #pragma unroll
    for (int j = 0; j < 8; j++)
        p[threadIdx.x + j * 256] = vals[j] * inv;
}

// ---------------------------------------------------------------------------
// Kernel 4: res = attn @ V. grid = (32 t-tiles, 8 batches), block = 256.
// K-loop only over s-tiles <= t-tile (causal zeros skipped).
// ---------------------------------------------------------------------------
__global__ void av_kernel(const float* __restrict__ attn, float* __restrict__ res) {
    const int t_t = blockIdx.x;
    const int b = blockIdx.y;

    __shared__ float sa[64][65];
    __shared__ float sv[64][65];

    const float* A = attn + (size_t)b * T_ * T_;
    const float* v = g_v + (size_t)b * T_ * H_;
    const int t0 = t_t * 64;

    const int tx = threadIdx.x & 15;
    const int ty = threadIdx.x >> 4;

    float acc[4][4] = {};

    for (int s_t = 0; s_t <= t_t; s_t++) {
        const int s0 = s_t * 64;
        for (int i = threadIdx.x; i < 64 * 64; i += 256) {
            int r = i >> 6, c = i & 63;
            sa[r][c] = A[(size_t)(t0 + r) * T_ + s0 + c];
            sv[r][c] = v[(size_t)(s0 + r) * H_ + c];
        }
        __syncthreads();

        #pragma unroll
        for (int kk = 0; kk < 64; kk++) {
            float a[4], bb[4];
            #pragma unroll
            for (int i = 0; i < 4; i++) a[i] = sa[ty * 4 + i][kk];
            #pragma unroll
            for (int j = 0; j < 4; j++) bb[j] = sv[kk][tx * 4 + j];
            #pragma unroll
            for (int i = 0; i < 4; i++)
                #pragma unroll
                for (int j = 0; j < 4; j++)
                    acc[i][j] = fmaf(a[i], bb[j], acc[i][j]);
        }
        __syncthreads();
    }

    #pragma unroll
    for (int i = 0; i < 4; i++) {
        size_t row = (size_t)b * T_ + t0 + ty * 4 + i;
        #pragma unroll
        for (int j = 0; j < 4; j++)
            res[row * H_ + tx * 4 + j] = acc[i][j];
    }
}

// ---------------------------------------------------------------------------
extern "C" void kernel_launch(void* const* d_in, const int* in_sizes, int n_in,
                              void* d_out, int out_size) {
    (void)in_sizes; (void)n_in;
    const float* x  = (const float*)d_in[0];
    const float* Wq = (const float*)d_in[1];
    const float* Wk = (const float*)d_in[2];
    const float* Wv = (const float*)d_in[3];

    const size_t n_res  = (size_t)B_ * T_ * H_;       // 1,048,576
    const size_t n_attn = (size_t)B_ * T_ * T_;       // 33,554,432

    float* attn_scratch = nullptr;
    float* res_scratch = nullptr;
    cudaGetSymbolAddress((void**)&attn_scratch, g_attn_scratch);
    cudaGetSymbolAddress((void**)&res_scratch, g_res);

    float* res;
    float* attn;
    if ((size_t)out_size == n_res + n_attn) {
        // tuple output: res first, then attn
        res  = (float*)d_out;
        attn = (float*)d_out + n_res;
    } else if ((size_t)out_size == n_attn) {
        attn = (float*)d_out;
        res  = res_scratch;
    } else {
        res  = (float*)d_out;
        attn = attn_scratch;
    }

    proj_kernel<<<dim3(NROWS / 64, 1, 3), 256>>>(x, Wq, Wk, Wv);
    scores_kernel<<<dim3(T_ / 64, T_ / 64, B_), 256>>>(attn);
    softmax_kernel<<<NROWS, 256>>>(attn);
    av_kernel<<<dim3(T_ / 64, B_), 256>>>(attn, res);
}

// round 2
// speedup vs baseline: 1.3928x; 1.3928x over previous
#include <cuda_runtime.h>
#include <math.h>

#define B_ 8
#define T_ 2048
#define C_ 1024
#define H_ 64
#define NROWS (B_ * T_)   // 16384

__device__ float g_q[NROWS * H_];
__device__ float g_k[NROWS * H_];
__device__ float g_v[NROWS * H_];
__device__ float g_res[NROWS * H_];
__device__ float g_attn_scratch[(size_t)B_ * T_ * T_];

typedef unsigned long long ull;

// ---- packed f32x2 helpers (sm_103a FFMA2) ----------------------------------
__device__ __forceinline__ ull pack_dup(float x) {
    ull r; unsigned u = __float_as_uint(x);
    asm("mov.b64 %0, {%1, %1};" : "=l"(r) : "r"(u));
    return r;
}
__device__ __forceinline__ void ffma2(ull& acc, ull a, ull b) {
    asm("fma.rn.f32x2 %0, %1, %2, %3;" : "=l"(acc) : "l"(a), "l"(b), "l"(acc));
}
__device__ __forceinline__ float2 unpack2(ull v) {
    unsigned lo, hi;
    asm("mov.b64 {%0, %1}, %2;" : "=r"(lo), "=r"(hi) : "l"(v));
    return make_float2(__uint_as_float(lo), __uint_as_float(hi));
}

// ---------------------------------------------------------------------------
// Kernel 1: QKV projection. grid=(128, 3), block=256, tile 128x64, K-chunk 64.
// Per thread: 4m x 8n (4 f32x2 pairs). smem: Xs[128][66] + Ws[64][64].
// ---------------------------------------------------------------------------
#define PROJ_SMEM (128*66*4 + 64*64*4)
__global__ __launch_bounds__(256) void proj_kernel(const float* __restrict__ x,
                                                   const float* __restrict__ Wq,
                                                   const float* __restrict__ Wk,
                                                   const float* __restrict__ Wv) {
    extern __shared__ float sm[];
    float* Xs = sm;             // [128][66]
    float* Ws = sm + 128 * 66;  // [64][64]

    const float* W; float* out;
    if (blockIdx.y == 0)      { W = Wq; out = g_q; }
    else if (blockIdx.y == 1) { W = Wk; out = g_k; }
    else                      { W = Wv; out = g_v; }

    const int row0 = blockIdx.x * 128;
    const int tid = threadIdx.x;
    const int tx = tid & 7;    // 8 groups of 8 h
    const int ty = tid >> 3;   // 32 groups of 4 rows

    ull acc[4][4] = {};

    for (int k0 = 0; k0 < C_; k0 += 64) {
        #pragma unroll
        for (int i = tid; i < 128 * 16; i += 256) {
            int r = i >> 4, c4 = i & 15;
            float4 v = *(const float4*)&x[(size_t)(row0 + r) * C_ + k0 + c4 * 4];
            float* d = &Xs[r * 66 + c4 * 4];
            *(float2*)d       = make_float2(v.x, v.y);
            *(float2*)(d + 2) = make_float2(v.z, v.w);
        }
        #pragma unroll
        for (int i = tid; i < 64 * 16; i += 256) {
            int r = i >> 4, c4 = i & 15;
            *(float4*)&Ws[r * 64 + c4 * 4] =
                *(const float4*)&W[(size_t)(k0 + r) * H_ + c4 * 4];
        }
        __syncthreads();

        #pragma unroll 4
        for (int kk = 0; kk < 64; kk++) {
            ull a[4];
            #pragma unroll
            for (int i = 0; i < 4; i++) a[i] = pack_dup(Xs[(ty * 4 + i) * 66 + kk]);
            ulonglong2 b01 = *(const ulonglong2*)&Ws[kk * 64 + tx * 8];
            ulonglong2 b23 = *(const ulonglong2*)&Ws[kk * 64 + tx * 8 + 4];
            ull bp[4] = {b01.x, b01.y, b23.x, b23.y};
            #pragma unroll
            for (int i = 0; i < 4; i++)
                #pragma unroll
                for (int p = 0; p < 4; p++) ffma2(acc[i][p], a[i], bp[p]);
        }
        __syncthreads();
    }

    #pragma unroll
    for (int i = 0; i < 4; i++) {
        size_t row = (size_t)(row0 + ty * 4 + i);
        float2 p0 = unpack2(acc[i][0]), p1 = unpack2(acc[i][1]);
        float2 p2 = unpack2(acc[i][2]), p3 = unpack2(acc[i][3]);
        *(float4*)&out[row * H_ + tx * 8]     = make_float4(p0.x, p0.y, p1.x, p1.y);
        *(float4*)&out[row * H_ + tx * 8 + 4] = make_float4(p2.x, p2.y, p3.x, p3.y);
    }
}

// ---------------------------------------------------------------------------
// Kernel 2: scores = Q@K^T / 32, lower-triangular 128x128 tiles.
// grid=(16,16,8) early-out upper. Per thread: 8t x 8s (4 pairs).
// smem: Qs[128][66] + Ks[64][130] (K transposed to h-major).
// ---------------------------------------------------------------------------
#define SCORES_SMEM (128*66*4 + 64*130*4)
__global__ __launch_bounds__(256, 2) void scores_kernel(float* __restrict__ attn) {
    const int s_t = blockIdx.x, t_t = blockIdx.y;
    if (s_t > t_t) return;
    const int b = blockIdx.z;

    extern __shared__ float sm[];
    float* Qs = sm;             // [128][66]
    float* Ks = sm + 128 * 66;  // [64][130]

    const float* q = g_q + (size_t)b * T_ * H_;
    const float* k = g_k + (size_t)b * T_ * H_;
    const int t0 = t_t * 128, s0 = s_t * 128;
    const int tid = threadIdx.x;
    const int tx = tid & 15;   // 16 groups of 8 s
    const int ty = tid >> 4;   // 16 groups of 8 t

    #pragma unroll
    for (int i = tid; i < 128 * 16; i += 256) {
        int r = i >> 4, c4 = i & 15;
        float4 v = *(const float4*)&q[(size_t)(t0 + r) * H_ + c4 * 4];
        float* d = &Qs[r * 66 + c4 * 4];
        *(float2*)d       = make_float2(v.x, v.y);
        *(float2*)(d + 2) = make_float2(v.z, v.w);
    }
    #pragma unroll
    for (int i = tid; i < 128 * 16; i += 256) {
        int s = i >> 4, h4 = i & 15;
        float4 v = *(const float4*)&k[(size_t)(s0 + s) * H_ + h4 * 4];
        Ks[(h4 * 4 + 0) * 130 + s] = v.x;
        Ks[(h4 * 4 + 1) * 130 + s] = v.y;
        Ks[(h4 * 4 + 2) * 130 + s] = v.z;
        Ks[(h4 * 4 + 3) * 130 + s] = v.w;
    }
    __syncthreads();

    ull acc[8][4] = {};
    #pragma unroll 2
    for (int kk = 0; kk < 64; kk++) {
        ull a[8];
        #pragma unroll
        for (int i = 0; i < 8; i++) a[i] = pack_dup(Qs[(ty * 8 + i) * 66 + kk]);
        ull bp[4];
        #pragma unroll
        for (int p = 0; p < 4; p++) bp[p] = *(const ull*)&Ks[kk * 130 + tx * 8 + p * 2];
        #pragma unroll
        for (int i = 0; i < 8; i++)
            #pragma unroll
            for (int p = 0; p < 4; p++) ffma2(acc[i][p], a[i], bp[p]);
    }

    const float sc = 0.03125f;  // 1/sqrt(1024)
    #pragma unroll
    for (int i = 0; i < 8; i++) {
        size_t row = (size_t)b * T_ + t0 + ty * 8 + i;
        float2 p0 = unpack2(acc[i][0]), p1 = unpack2(acc[i][1]);
        float2 p2 = unpack2(acc[i][2]), p3 = unpack2(acc[i][3]);
        *(float4*)&attn[row * T_ + s0 + tx * 8] =
            make_float4(p0.x * sc, p0.y * sc, p1.x * sc, p1.y * sc);
        *(float4*)&attn[row * T_ + s0 + tx * 8 + 4] =
            make_float4(p2.x * sc, p2.y * sc, p3.x * sc, p3.y * sc);
    }
}

// ---------------------------------------------------------------------------
// Kernel 3: row-wise causal softmax, in place, float4.
// ---------------------------------------------------------------------------
__global__ void softmax_kernel(float* __restrict__ attn) {
    const int row = blockIdx.x;
    const int t = row & (T_ - 1);
    float* p = attn + (size_t)row * T_;

    __shared__ float red_max[8];
    __shared__ float red_sum[8];

    float4 v[2];
    float mx = -INFINITY;
    #pragma unroll
    for (int j = 0; j < 2; j++) {
        int s = (threadIdx.x + j * 256) * 4;
        float4 f = *(const float4*)&p[s];
        v[j].x = (s + 0 <= t) ? f.x : -INFINITY;
        v[j].y = (s + 1 <= t) ? f.y : -INFINITY;
        v[j].z = (s + 2 <= t) ? f.z : -INFINITY;
        v[j].w = (s + 3 <= t) ? f.w : -INFINITY;
        mx = fmaxf(mx, fmaxf(fmaxf(v[j].x, v[j].y), fmaxf(v[j].z, v[j].w)));
    }
    #pragma unroll
    for (int o = 16; o; o >>= 1) mx = fmaxf(mx, __shfl_xor_sync(0xffffffffu, mx, o));
    if ((threadIdx.x & 31) == 0) red_max[threadIdx.x >> 5] = mx;
    __syncthreads();
    float m = red_max[0];
    #pragma unroll
    for (int w = 1; w < 8; w++) m = fmaxf(m, red_max[w]);

    float sum = 0.f;
    #pragma unroll
    for (int j = 0; j < 2; j++) {
        v[j].x = __expf(v[j].x - m);
        v[j].y = __expf(v[j].y - m);
        v[j].z = __expf(v[j].z - m);
        v[j].w = __expf(v[j].w - m);
        sum += (v[j].x + v[j].y) + (v[j].z + v[j].w);
    }
    #pragma unroll
    for (int o = 16; o; o >>= 1) sum += __shfl_xor_sync(0xffffffffu, sum, o);
    if ((threadIdx.x & 31) == 0) red_sum[threadIdx.x >> 5] = sum;
    __syncthreads();
    float total = 0.f;
    #pragma unroll
    for (int w = 0; w < 8; w++) total += red_sum[w];

    const float inv = 1.f / total;
    #pragma unroll
    for (int j = 0; j < 2; j++) {
        int s = (threadIdx.x + j * 256) * 4;
        *(float4*)&p[s] = make_float4(v[j].x * inv, v[j].y * inv, v[j].z * inv, v[j].w * inv);
    }
}

// ---------------------------------------------------------------------------
// Kernel 4: res += attn @ V, split-K. grid=(16 chunks, 16 t-tiles, 8) early-out.
// Each block: 128t x 64h output x 128s K-chunk, atomicAdd into res.
// smem: As(attn)[128][130] + Vs[128][64].
// ---------------------------------------------------------------------------
#define AV_SMEM (128*130*4 + 128*64*4)
__global__ __launch_bounds__(256, 2) void av_kernel(const float* __restrict__ attn,
                                                    float* __restrict__ res) {
    const int c_t = blockIdx.x, t_t = blockIdx.y;
    if (c_t > t_t) return;
    const int b = blockIdx.z;

    extern __shared__ float sm[];
    float* As = sm;              // [128][130]
    float* Vs = sm + 128 * 130;  // [128][64]

    const int t0 = t_t * 128, s0 = c_t * 128;
    const float* A = attn + (size_t)b * T_ * T_;
    const float* v = g_v + (size_t)b * T_ * H_;
    const int tid = threadIdx.x;
    const int tx = tid & 7;    // 8 groups of 8 h
    const int ty = tid >> 3;   // 32 groups of 4 t

    #pragma unroll
    for (int i = tid; i < 128 * 32; i += 256) {
        int r = i >> 5, c4 = i & 31;
        float4 val = *(const float4*)&A[(size_t)(t0 + r) * T_ + s0 + c4 * 4];
        float* d = &As[r * 130 + c4 * 4];
        *(float2*)d       = make_float2(val.x, val.y);
        *(float2*)(d + 2) = make_float2(val.z, val.w);
    }
    #pragma unroll
    for (int i = tid; i < 128 * 16; i += 256) {
        int r = i >> 4, c4 = i & 15;
        *(float4*)&Vs[r * 64 + c4 * 4] = *(const float4*)&v[(size_t)(s0 + r) * H_ + c4 * 4];
    }
    __syncthreads();

    ull acc[4][4] = {};
    #pragma unroll 4
    for (int kk = 0; kk < 128; kk++) {
        ull a[4];
        #pragma unroll
        for (int i = 0; i < 4; i++) a[i] = pack_dup(As[(ty * 4 + i) * 130 + kk]);
        ulonglong2 b01 = *(const ulonglong2*)&Vs[kk * 64 + tx * 8];
        ulonglong2 b23 = *(const ulonglong2*)&Vs[kk * 64 + tx * 8 + 4];
        ull bp[4] = {b01.x, b01.y, b23.x, b23.y};
        #pragma unroll
        for (int i = 0; i < 4; i++)
            #pragma unroll
            for (int p = 0; p < 4; p++) ffma2(acc[i][p], a[i], bp[p]);
    }

    #pragma unroll
    for (int i = 0; i < 4; i++) {
        size_t row = (size_t)b * T_ + t0 + ty * 4 + i;
        #pragma unroll
        for (int p = 0; p < 4; p++) {
            float2 f = unpack2(acc[i][p]);
            atomicAdd(&res[row * H_ + tx * 8 + p * 2],     f.x);
            atomicAdd(&res[row * H_ + tx * 8 + p * 2 + 1], f.y);
        }
    }
}

// ---------------------------------------------------------------------------
extern "C" void kernel_launch(void* const* d_in, const int* in_sizes, int n_in,
                              void* d_out, int out_size) {
    (void)in_sizes; (void)n_in;
    const float* x  = (const float*)d_in[0];
    const float* Wq = (const float*)d_in[1];
    const float* Wk = (const float*)d_in[2];
    const float* Wv = (const float*)d_in[3];

    const size_t n_res  = (size_t)B_ * T_ * H_;
    const size_t n_attn = (size_t)B_ * T_ * T_;

    float* attn_scratch = nullptr;
    float* res_scratch = nullptr;
    cudaGetSymbolAddress((void**)&attn_scratch, g_attn_scratch);
    cudaGetSymbolAddress((void**)&res_scratch, g_res);

    float* res;
    float* attn;
    if ((size_t)out_size == n_res + n_attn) {
        res  = (float*)d_out;
        attn = (float*)d_out + n_res;
    } else if ((size_t)out_size == n_attn) {
        attn = (float*)d_out;
        res  = res_scratch;
    } else {
        res  = (float*)d_out;
        attn = attn_scratch;
    }

    cudaFuncSetAttribute(proj_kernel,   cudaFuncAttributeMaxDynamicSharedMemorySize, PROJ_SMEM);
    cudaFuncSetAttribute(scores_kernel, cudaFuncAttributeMaxDynamicSharedMemorySize, SCORES_SMEM);
    cudaFuncSetAttribute(av_kernel,     cudaFuncAttributeMaxDynamicSharedMemorySize, AV_SMEM);

    cudaMemsetAsync(res, 0, n_res * sizeof(float));
    proj_kernel<<<dim3(128, 3), 256, PROJ_SMEM>>>(x, Wq, Wk, Wv);
    scores_kernel<<<dim3(16, 16, 8), 256, SCORES_SMEM>>>(attn);
    softmax_kernel<<<NROWS, 256>>>(attn);
    av_kernel<<<dim3(16, 16, 8), 256, AV_SMEM>>>(attn, res);
}

// round 3
// speedup vs baseline: 1.6536x; 1.1873x over previous
#include <cuda_runtime.h>
#include <math.h>

#define B_ 8
#define T_ 2048
#define C_ 1024
#define H_ 64
#define NROWS (B_ * T_)   // 16384

__device__ float g_q[NROWS * H_];
__device__ float g_k[NROWS * H_];
__device__ float g_v[NROWS * H_];
__device__ float g_res[NROWS * H_];
__device__ float g_rowsum[NROWS];
__device__ float g_attn_scratch[(size_t)B_ * T_ * T_];

typedef unsigned long long ull;

__device__ __forceinline__ ull pack_dup(float x) {
    ull r; unsigned u = __float_as_uint(x);
    asm("mov.b64 %0, {%1, %1};" : "=l"(r) : "r"(u));
    return r;
}
__device__ __forceinline__ void ffma2(ull& acc, ull a, ull b) {
    asm("fma.rn.f32x2 %0, %1, %2, %3;" : "=l"(acc) : "l"(a), "l"(b), "l"(acc));
}
__device__ __forceinline__ float2 unpack2(ull v) {
    unsigned lo, hi;
    asm("mov.b64 {%0, %1}, %2;" : "=r"(lo), "=r"(hi) : "l"(v));
    return make_float2(__uint_as_float(lo), __uint_as_float(hi));
}

// ---------------------------------------------------------------------------
// Kernel 1: QKV projection. grid=(64, 3), block=256, tile 256m x 64h, K-chunk 64.
// Per thread 8m x 8n. Xs_T is kk-major so M-side loads are LDS.128.
// ---------------------------------------------------------------------------
#define XT_P 260
#define PROJ_SMEM (64 * XT_P * 4 + 64 * 64 * 4)
__global__ __launch_bounds__(256, 2) void proj_kernel(const float* __restrict__ x,
                                                      const float* __restrict__ Wq,
                                                      const float* __restrict__ Wk,
                                                      const float* __restrict__ Wv) {
    extern __shared__ float sm[];
    float* Xs_T = sm;              // [64 kk][260]
    float* Ws   = sm + 64 * XT_P;  // [64 kk][64 h]

    const float* W; float* out;
    if (blockIdx.y == 0)      { W = Wq; out = g_q; }
    else if (blockIdx.y == 1) { W = Wk; out = g_k; }
    else                      { W = Wv; out = g_v; }

    const int row0 = blockIdx.x * 256;
    const int tid = threadIdx.x;
    const int tx = tid & 7;    // 8 h-groups of 8
    const int ty = tid >> 3;   // 32 m-groups of 8

    const int lc  = tid & 63;  // load: column (kk) within chunk
    const int lmg = tid >> 6;  // load: m-quad group 0..3

    ull acc[8][4] = {};

    for (int k0 = 0; k0 < C_; k0 += 64) {
        // X chunk [256 m][64 kk] -> Xs_T[kk][m], float4 along m
        #pragma unroll
        for (int it = 0; it < 16; it++) {
            int m4 = (it * 4 + lmg) * 4;
            const float* xp = &x[(size_t)(row0 + m4) * C_ + k0 + lc];
            float a0 = xp[0];
            float a1 = xp[C_];
            float a2 = xp[2 * C_];
            float a3 = xp[3 * C_];
            *(float4*)&Xs_T[lc * XT_P + m4] = make_float4(a0, a1, a2, a3);
        }
        // W chunk [64 kk][64 h]
        #pragma unroll
        for (int i = tid; i < 64 * 16; i += 256) {
            int r = i >> 4, c4 = i & 15;
            *(float4*)&Ws[r * 64 + c4 * 4] =
                *(const float4*)&W[(size_t)(k0 + r) * H_ + c4 * 4];
        }
        __syncthreads();

        #pragma unroll 4
        for (int kk = 0; kk < 64; kk++) {
            float4 a0 = *(const float4*)&Xs_T[kk * XT_P + ty * 8];
            float4 a1 = *(const float4*)&Xs_T[kk * XT_P + ty * 8 + 4];
            ull am[8];
            am[0] = pack_dup(a0.x); am[1] = pack_dup(a0.y);
            am[2] = pack_dup(a0.z); am[3] = pack_dup(a0.w);
            am[4] = pack_dup(a1.x); am[5] = pack_dup(a1.y);
            am[6] = pack_dup(a1.z); am[7] = pack_dup(a1.w);
            ulonglong2 b01 = *(const ulonglong2*)&Ws[kk * 64 + tx * 8];
            ulonglong2 b23 = *(const ulonglong2*)&Ws[kk * 64 + tx * 8 + 4];
            ull bp[4] = {b01.x, b01.y, b23.x, b23.y};
            #pragma unroll
            for (int m = 0; m < 8; m++)
                #pragma unroll
                for (int p = 0; p < 4; p++) ffma2(acc[m][p], am[m], bp[p]);
        }
        __syncthreads();
    }

    #pragma unroll
    for (int m = 0; m < 8; m++) {
        size_t row = (size_t)(row0 + ty * 8 + m);
        float2 p0 = unpack2(acc[m][0]), p1 = unpack2(acc[m][1]);
        float2 p2 = unpack2(acc[m][2]), p3 = unpack2(acc[m][3]);
        *(float4*)&out[row * H_ + tx * 8]     = make_float4(p0.x, p0.y, p1.x, p1.y);
        *(float4*)&out[row * H_ + tx * 8 + 4] = make_float4(p2.x, p2.y, p3.x, p3.y);
    }
}

// ---------------------------------------------------------------------------
// Kernel 2: E = exp(Q@K^T / 32) for lower tiles, zeros for upper/masked.
// Also accumulates per-row sums into g_rowsum via atomics.
// grid=(16 s,16 t,8 b), block=256, tile 128x128, per thread 8t x 8s.
// ---------------------------------------------------------------------------
#define QT_P 132
#define SCORES_SMEM (2 * 64 * QT_P * 4)
__global__ __launch_bounds__(256, 2) void scores_kernel(float* __restrict__ attn) {
    const int s_t = blockIdx.x, t_t = blockIdx.y;
    const int b = blockIdx.z;
    const int t0 = t_t * 128, s0 = s_t * 128;
    const int tid = threadIdx.x;

    if (s_t > t_t) {  // upper triangle: pure zero fill
        #pragma unroll
        for (int i = tid; i < 128 * 32; i += 256) {
            int r = i >> 5, c4 = i & 31;
            *(float4*)&attn[((size_t)b * T_ + t0 + r) * T_ + s0 + c4 * 4] =
                make_float4(0.f, 0.f, 0.f, 0.f);
        }
        return;
    }

    extern __shared__ float sm[];
    float* Qs_T = sm;               // [64 h][132 t]
    float* Ks_T = sm + 64 * QT_P;   // [64 h][132 s]

    const float* q = g_q + (size_t)b * T_ * H_;
    const float* k = g_k + (size_t)b * T_ * H_;

    const int lh = tid & 63;
    const int lg = tid >> 6;   // 0..3
    #pragma unroll
    for (int it = 0; it < 8; it++) {
        int r4 = (it * 4 + lg) * 4;
        const float* qp = &q[(size_t)(t0 + r4) * H_ + lh];
        *(float4*)&Qs_T[lh * QT_P + r4] =
            make_float4(qp[0], qp[H_], qp[2 * H_], qp[3 * H_]);
        const float* kp = &k[(size_t)(s0 + r4) * H_ + lh];
        *(float4*)&Ks_T[lh * QT_P + r4] =
            make_float4(kp[0], kp[H_], kp[2 * H_], kp[3 * H_]);
    }
    __syncthreads();

    const int tx = tid & 15;   // 16 s-groups of 8
    const int ty = tid >> 4;   // 16 t-groups of 8

    ull acc[8][4] = {};
    #pragma unroll 2
    for (int kk = 0; kk < 64; kk++) {
        float4 a0 = *(const float4*)&Qs_T[kk * QT_P + ty * 8];
        float4 a1 = *(const float4*)&Qs_T[kk * QT_P + ty * 8 + 4];
        ull am[8];
        am[0] = pack_dup(a0.x); am[1] = pack_dup(a0.y);
        am[2] = pack_dup(a0.z); am[3] = pack_dup(a0.w);
        am[4] = pack_dup(a1.x); am[5] = pack_dup(a1.y);
        am[6] = pack_dup(a1.z); am[7] = pack_dup(a1.w);
        ulonglong2 b01 = *(const ulonglong2*)&Ks_T[kk * QT_P + tx * 8];
        ulonglong2 b23 = *(const ulonglong2*)&Ks_T[kk * QT_P + tx * 8 + 4];
        ull bp[4] = {b01.x, b01.y, b23.x, b23.y};
        #pragma unroll
        for (int i = 0; i < 8; i++)
            #pragma unroll
            for (int p = 0; p < 4; p++) ffma2(acc[i][p], am[i], bp[p]);
    }

    const float sc = 0.03125f;  // 1/sqrt(1024)
    const bool diag = (s_t == t_t);
    #pragma unroll
    for (int i = 0; i < 8; i++) {
        const int tglob = t0 + ty * 8 + i;
        const size_t row = (size_t)b * T_ + tglob;
        float e[8];
        #pragma unroll
        for (int p = 0; p < 4; p++) {
            float2 f = unpack2(acc[i][p]);
            int sg = s0 + tx * 8 + p * 2;
            e[p * 2]     = (!diag || sg     <= tglob) ? __expf(f.x * sc) : 0.f;
            e[p * 2 + 1] = (!diag || sg + 1 <= tglob) ? __expf(f.y * sc) : 0.f;
        }
        float rs = ((e[0] + e[1]) + (e[2] + e[3])) + ((e[4] + e[5]) + (e[6] + e[7]));
        #pragma unroll
        for (int off = 8; off; off >>= 1) rs += __shfl_xor_sync(0xffffffffu, rs, off);
        if (tx == 0) atomicAdd(&g_rowsum[row], rs);
        *(float4*)&attn[row * T_ + s0 + tx * 8]     = make_float4(e[0], e[1], e[2], e[3]);
        *(float4*)&attn[row * T_ + s0 + tx * 8 + 4] = make_float4(e[4], e[5], e[6], e[7]);
    }
}

// ---------------------------------------------------------------------------
// Kernel 3: normalize lower-triangular part of each row by 1/rowsum.
// grid = NROWS blocks, 256 threads. Entries past t are zeros; scaling keeps 0,
// so we only touch quads up to t's quad.
// ---------------------------------------------------------------------------
__global__ void normalize_kernel(float* __restrict__ attn) {
    const int row = blockIdx.x;
    const int t = row & (T_ - 1);
    const float inv = 1.f / g_rowsum[row];
    float4* p = (float4*)(attn + (size_t)row * T_);
    const int nq = (t >> 2) + 1;
    for (int i = threadIdx.x; i < nq; i += 256) {
        float4 v = p[i];
        p[i] = make_float4(v.x * inv, v.y * inv, v.z * inv, v.w * inv);
    }
}

// ---------------------------------------------------------------------------
// Kernel 4: res += attn @ V, split-K. grid=(16 s-chunks, 16 t-tiles, 8).
// Tile 128t x 64h x 128s, per thread 4t x 8h. As_T is s(kk)-major.
// ---------------------------------------------------------------------------
#define AT_P 132
#define AV_SMEM (128 * AT_P * 4 + 128 * 64 * 4)
__global__ __launch_bounds__(256, 2) void av_kernel(const float* __restrict__ attn,
                                                    float* __restrict__ res) {
    const int c_t = blockIdx.x, t_t = blockIdx.y;
    if (c_t > t_t) return;
    const int b = blockIdx.z;

    extern __shared__ float sm[];
    float* As_T = sm;                // [128 s][132 t]
    float* Vs   = sm + 128 * AT_P;   // [128 s][64 h]

    const int t0 = t_t * 128, s0 = c_t * 128;
    const float* A = attn + (size_t)b * T_ * T_;
    const float* v = g_v + (size_t)b * T_ * H_;
    const int tid = threadIdx.x;

    {
        const int ls = tid & 127;
        const int lg = tid >> 7;   // 0..1
        #pragma unroll
        for (int it = 0; it < 16; it++) {
            int t4 = (it * 2 + lg) * 4;
            const float* ap = &A[(size_t)(t0 + t4) * T_ + s0 + ls];
            *(float4*)&As_T[ls * AT_P + t4] =
                make_float4(ap[0], ap[T_], ap[2 * T_], ap[3 * T_]);
        }
        #pragma unroll
        for (int i = tid; i < 128 * 16; i += 256) {
            int r = i >> 4, c4 = i & 15;
            *(float4*)&Vs[r * 64 + c4 * 4] =
                *(const float4*)&v[(size_t)(s0 + r) * H_ + c4 * 4];
        }
    }
    __syncthreads();

    const int tx = tid & 7;    // 8 h-groups of 8
    const int ty = tid >> 3;   // 32 t-groups of 4

    ull acc[4][4] = {};
    #pragma unroll 4
    for (int kk = 0; kk < 128; kk++) {
        float4 a = *(const float4*)&As_T[kk * AT_P + ty * 4];
        ull am[4] = {pack_dup(a.x), pack_dup(a.y), pack_dup(a.z), pack_dup(a.w)};
        ulonglong2 b01 = *(const ulonglong2*)&Vs[kk * 64 + tx * 8];
        ulonglong2 b23 = *(const ulonglong2*)&Vs[kk * 64 + tx * 8 + 4];
        ull bp[4] = {b01.x, b01.y, b23.x, b23.y};
        #pragma unroll
        for (int i = 0; i < 4; i++)
            #pragma unroll
            for (int p = 0; p < 4; p++) ffma2(acc[i][p], am[i], bp[p]);
    }

    #pragma unroll
    for (int i = 0; i < 4; i++) {
        size_t row = (size_t)b * T_ + t0 + ty * 4 + i;
        #pragma unroll
        for (int p = 0; p < 4; p++) {
            float2 f = unpack2(acc[i][p]);
            atomicAdd(&res[row * H_ + tx * 8 + p * 2],     f.x);
            atomicAdd(&res[row * H_ + tx * 8 + p * 2 + 1], f.y);
        }
    }
}

// ---------------------------------------------------------------------------
extern "C" void kernel_launch(void* const* d_in, const int* in_sizes, int n_in,
                              void* d_out, int out_size) {
    (void)in_sizes; (void)n_in;
    const float* x  = (const float*)d_in[0];
    const float* Wq = (const float*)d_in[1];
    const float* Wk = (const float*)d_in[2];
    const float* Wv = (const float*)d_in[3];

    const size_t n_res  = (size_t)B_ * T_ * H_;
    const size_t n_attn = (size_t)B_ * T_ * T_;

    float* attn_scratch = nullptr;
    float* res_scratch = nullptr;
    float* rowsum = nullptr;
    cudaGetSymbolAddress((void**)&attn_scratch, g_attn_scratch);
    cudaGetSymbolAddress((void**)&res_scratch, g_res);
    cudaGetSymbolAddress((void**)&rowsum, g_rowsum);

    float* res;
    float* attn;
    if ((size_t)out_size == n_res + n_attn) {
        res  = (float*)d_out;
        attn = (float*)d_out + n_res;
    } else if ((size_t)out_size == n_attn) {
        attn = (float*)d_out;
        res  = res_scratch;
    } else {
        res  = (float*)d_out;
        attn = attn_scratch;
    }

    cudaFuncSetAttribute(proj_kernel,   cudaFuncAttributeMaxDynamicSharedMemorySize, PROJ_SMEM);
    cudaFuncSetAttribute(scores_kernel, cudaFuncAttributeMaxDynamicSharedMemorySize, SCORES_SMEM);
    cudaFuncSetAttribute(av_kernel,     cudaFuncAttributeMaxDynamicSharedMemorySize, AV_SMEM);

    cudaMemsetAsync(rowsum, 0, NROWS * sizeof(float));
    cudaMemsetAsync(res, 0, n_res * sizeof(float));
    proj_kernel<<<dim3(64, 3), 256, PROJ_SMEM>>>(x, Wq, Wk, Wv);
    scores_kernel<<<dim3(16, 16, 8), 256, SCORES_SMEM>>>(attn);
    normalize_kernel<<<NROWS, 256>>>(attn);
    av_kernel<<<dim3(16, 16, 8), 256, AV_SMEM>>>(attn, res);
}